// round 3
// baseline (speedup 1.0000x reference)
#include <cuda_runtime.h>
#include <stdint.h>

#define B_SZ 65536
#define NM 5
#define WPB 8
#define NBLOCKS (B_SZ / WPB)  // 8192

__device__ float g_partials[NBLOCKS];
__device__ unsigned g_count;   // zero-init; self-resets each launch

__device__ __forceinline__ float sqrt_ap(float x) {
    float r;
    asm("sqrt.approx.f32 %0, %1;" : "=f"(r) : "f"(x));
    return r;
}

// Smooth-L1 (huber, delta=1): ad<1 ? 0.5 d^2 : ad-0.5 == t*(ad - 0.5t), t=min(ad,1)
__device__ __forceinline__ float huber(float d) {
    float ad = fabsf(d);
    float t = fminf(ad, 1.0f);
    return t * fmaf(-0.5f, t, ad);
}

__device__ __forceinline__ uint32_t rotl32(uint32_t x, uint32_t d) {
    return __funnelshift_l(x, x, d);
}

// JAX partitionable ThreeFry-2x32: key=(0,42), counter=(0,i); randint(0,5) -> (x0^x1) % 5
__device__ __forceinline__ int threefry_mod5(uint32_t i) {
    const uint32_t k0 = 0u, k1 = 42u;
    const uint32_t k2 = k0 ^ k1 ^ 0x1BD11BDAu;
    uint32_t x0 = k0;
    uint32_t x1 = i + k1;
#define TF4(r0, r1, r2, r3)                           \
    x0 += x1; x1 = rotl32(x1, r0); x1 ^= x0;          \
    x0 += x1; x1 = rotl32(x1, r1); x1 ^= x0;          \
    x0 += x1; x1 = rotl32(x1, r2); x1 ^= x0;          \
    x0 += x1; x1 = rotl32(x1, r3); x1 ^= x0;
    TF4(13, 15, 26, 6)   x0 += k1; x1 += k2 + 1u;
    TF4(17, 29, 16, 24)  x0 += k2; x1 += k0 + 2u;
    TF4(13, 15, 26, 6)   x0 += k0; x1 += k1 + 3u;
    TF4(17, 29, 16, 24)  x0 += k1; x1 += k2 + 4u;
    TF4(13, 15, 26, 6)   x0 += k2; x1 += k0 + 5u;
#undef TF4
    return (int)((x0 ^ x1) % 5u);
}

__global__ void __launch_bounds__(32 * WPB)
combo_fused(const float* __restrict__ path_pred,
            const float* __restrict__ path_gt,
            const float* __restrict__ cr_pred,
            const float* __restrict__ cr_gt,
            float* __restrict__ out) {
    __shared__ float warp_sums[WPB];
    __shared__ bool  is_last;
    const unsigned FULL = 0xffffffffu;
    int lane = threadIdx.x & 31;
    int w = threadIdx.x >> 5;
    int s = blockIdx.x * WPB + w;

    const float* tp = path_pred + (size_t)s * 505;                   // 5*50*2 traj + 5 probs
    const float2* gt2 = (const float2*)(path_gt + (size_t)s * 100);  // 400B rows: 8B aligned

    // lane handles t = lane (always) and t = 32+lane (lane < 18)
    float2 g0 = gt2[lane];
    bool has2 = (lane < 18);
    float2 g1 = make_float2(0.f, 0.f);
    if (has2) g1 = gt2[32 + lane];

    bool vec = ((s & 1) == 0);             // tp is 8B-aligned iff s even (505-float stride)
    const float* b0 = tp + 2 * lane;
    const float* b1 = tp + 2 * (32 + lane);

    float dist[NM], regs[NM], tlx[NM], tly[NM];
#pragma unroll
    for (int m = 0; m < NM; m++) {
        float x0, y0, x1v = 0.f, y1v = 0.f;
        if (vec) {
            float2 q0 = *(const float2*)(b0 + m * 100);
            x0 = q0.x; y0 = q0.y;
            if (has2) {
                float2 q1 = *(const float2*)(b1 + m * 100);
                x1v = q1.x; y1v = q1.y;
            }
        } else {
            x0 = b0[m * 100]; y0 = b0[m * 100 + 1];
            if (has2) { x1v = b1[m * 100]; y1v = b1[m * 100 + 1]; }
        }
        float dx = x0 - g0.x, dy = y0 - g0.y;
        float dsum = sqrt_ap(fmaf(dx, dx, dy * dy));
        float rsum = huber(dx) + huber(dy);
        if (has2) {
            float ex = x1v - g1.x, ey = y1v - g1.y;
            dsum += sqrt_ap(fmaf(ex, ex, ey * ey));
            rsum += huber(ex) + huber(ey);
        }
#pragma unroll
        for (int o = 16; o; o >>= 1) {
            dsum += __shfl_xor_sync(FULL, dsum, o);
            rsum += __shfl_xor_sync(FULL, rsum, o);
        }
        dist[m] = dsum;                        // sum over t (argmin-invariant scale)
        regs[m] = rsum;                        // sum of huber over 50x2
        tlx[m] = __shfl_sync(FULL, x1v, 17);   // traj[m][49] lives on lane 17
        tly[m] = __shfl_sync(FULL, y1v, 17);
    }
    float refx = __shfl_sync(FULL, g1.x, 17);  // path_gt[49]
    float refy = __shfl_sync(FULL, g1.y, 17);
    float rn = sqrt_ap(fmaf(refx, refx, refy * refy));
    bool ref_nan = isnan(refx) || isnan(refy);

    // eligible  <=>  angle <= 5deg  <=>  dot >= cos(5deg)*nprod  (nprod>0, no NaN)
    const float COS5 = 0.99619469809174553f;
    const float INF = __int_as_float(0x7f800000);
    float bestKey = INF;
    int best = 0;
    bool any = false;
#pragma unroll
    for (int m = 0; m < NM; m++) {
        float tn = sqrt_ap(fmaf(tlx[m], tlx[m], tly[m] * tly[m]));
        float nprod = rn * tn;
        float dot = fmaf(refx, tlx[m], refy * tly[m]);
        bool nanm = ref_nan || isnan(tlx[m]) || isnan(tly[m]);
        bool elig;
        if (nanm)               elig = false;          // angle := 180 - eps
        else if (nprod == 0.f)  elig = true;           // angle := 0
        else                    elig = (dot >= COS5 * nprod);
        any |= elig;
        float key = elig ? dist[m] : INF;
        if (key < bestKey) { bestKey = key; best = m; }  // strict < => first-min like argmin
    }
    if (!any) best = threefry_mod5((uint32_t)s);

    // cross-entropy via log_softmax over 5 logits; octet butterfly (each octet self-contained)
    float pr = (lane < NM) ? tp[500 + lane] : -INF;
    float mx = pr;
#pragma unroll
    for (int o = 4; o; o >>= 1) mx = fmaxf(mx, __shfl_xor_sync(FULL, mx, o));
    float e = (lane < NM) ? __expf(pr - mx) : 0.f;
#pragma unroll
    for (int o = 4; o; o >>= 1) e += __shfl_xor_sync(FULL, e, o);
    float pbest = __shfl_sync(FULL, pr, best);

    float rb = regs[0];
#pragma unroll
    for (int m = 1; m < NM; m++) rb = (best == m) ? regs[m] : rb;

    if (lane == 0) {
        float ce = (mx + __logf(e)) - pbest;
        float p = cr_pred[s], y = cr_gt[s];
        float lp  = fmaxf(__logf(p), -100.0f);
        float l1p = fmaxf(log1pf(-p), -100.0f);
        float bce = -(y * lp + (1.0f - y) * l1p);
        warp_sums[w] = ce + rb * 0.01f + bce;          // /100 = mean over (50,2)
    }
    __syncthreads();
    if (threadIdx.x == 0) {
        float t = 0.f;
#pragma unroll
        for (int i = 0; i < WPB; i++) t += warp_sums[i];
        g_partials[blockIdx.x] = t;
        __threadfence();
        unsigned done = atomicAdd(&g_count, 1u);
        is_last = (done == NBLOCKS - 1);
    }
    __syncthreads();

    if (is_last) {
        // deterministic finalize: fixed-order strided sums + fixed tree
        __shared__ float sm[32 * WPB];
        float t = 0.f;
        for (int i = threadIdx.x; i < NBLOCKS; i += 32 * WPB) t += g_partials[i];
        sm[threadIdx.x] = t;
        __syncthreads();
        for (int st = (32 * WPB) / 2; st; st >>= 1) {
            if ((int)threadIdx.x < st) sm[threadIdx.x] += sm[threadIdx.x + st];
            __syncthreads();
        }
        if (threadIdx.x == 0) {
            out[0] = sm[0] * (1.0f / (float)B_SZ);
            g_count = 0;                               // reset for next graph replay
        }
    }
}

extern "C" void kernel_launch(void* const* d_in, const int* in_sizes, int n_in,
                              void* d_out, int out_size) {
    const float* path_pred = (const float*)d_in[0];
    const float* path_gt   = (const float*)d_in[1];
    const float* cr_pred   = (const float*)d_in[2];
    const float* cr_gt     = (const float*)d_in[3];
    // d_in[4] = log_vars (unused by the reference's returned value)
    combo_fused<<<NBLOCKS, 32 * WPB>>>(path_pred, path_gt, cr_pred, cr_gt, (float*)d_out);
}

// round 4
// speedup vs baseline: 1.1572x; 1.1572x over previous
#include <cuda_runtime.h>
#include <stdint.h>

#define B_SZ 65536
#define NM 5
#define WPB 8
#define NBLOCKS (B_SZ / WPB)  // 8192

__device__ float g_partials[NBLOCKS];

__device__ __forceinline__ float sqrt_ap(float x) {
    float r;
    asm("sqrt.approx.f32 %0, %1;" : "=f"(r) : "f"(x));
    return r;
}

// Smooth-L1 (huber, delta=1): ad<1 ? 0.5 d^2 : ad-0.5 == t*(ad - 0.5t), t=min(ad,1)
__device__ __forceinline__ float huber(float d) {
    float ad = fabsf(d);
    float t = fminf(ad, 1.0f);
    return t * fmaf(-0.5f, t, ad);
}

__device__ __forceinline__ uint32_t rotl32(uint32_t x, uint32_t d) {
    return __funnelshift_l(x, x, d);
}

// JAX partitionable ThreeFry-2x32: key=(0,42), counter=(0,i); randint(0,5) -> (x0^x1) % 5
__device__ __forceinline__ int threefry_mod5(uint32_t i) {
    const uint32_t k0 = 0u, k1 = 42u;
    const uint32_t k2 = k0 ^ k1 ^ 0x1BD11BDAu;
    uint32_t x0 = k0;
    uint32_t x1 = i + k1;
#define TF4(r0, r1, r2, r3)                           \
    x0 += x1; x1 = rotl32(x1, r0); x1 ^= x0;          \
    x0 += x1; x1 = rotl32(x1, r1); x1 ^= x0;          \
    x0 += x1; x1 = rotl32(x1, r2); x1 ^= x0;          \
    x0 += x1; x1 = rotl32(x1, r3); x1 ^= x0;
    TF4(13, 15, 26, 6)   x0 += k1; x1 += k2 + 1u;
    TF4(17, 29, 16, 24)  x0 += k2; x1 += k0 + 2u;
    TF4(13, 15, 26, 6)   x0 += k0; x1 += k1 + 3u;
    TF4(17, 29, 16, 24)  x0 += k1; x1 += k2 + 4u;
    TF4(13, 15, 26, 6)   x0 += k2; x1 += k0 + 5u;
#undef TF4
    return (int)((x0 ^ x1) % 5u);
}

__global__ void __launch_bounds__(32 * WPB)
combo_main(const float* __restrict__ path_pred,
           const float* __restrict__ path_gt,
           const float* __restrict__ cr_pred,
           const float* __restrict__ cr_gt) {
    __shared__ float warp_sums[WPB];
    const unsigned FULL = 0xffffffffu;
    int lane = threadIdx.x & 31;
    int w = threadIdx.x >> 5;
    int s = blockIdx.x * WPB + w;

    const float* tp = path_pred + (size_t)s * 505;                   // 5*50*2 traj + 5 probs
    const float2* gt2 = (const float2*)(path_gt + (size_t)s * 100);  // 400B rows: 8B aligned

    // lane handles t = lane (always) and t = 32+lane (lane < 18)
    float2 g0 = gt2[lane];
    bool has2 = (lane < 18);
    float2 g1 = make_float2(0.f, 0.f);
    if (has2) g1 = gt2[32 + lane];

    const float* b0 = tp + 2 * lane;           // scalar loads: 505-float rows, odd alignment
    const float* b1 = tp + 2 * (32 + lane);

    // ---- main loop: distances only (regs deferred to after argmin) ----
    float dist[NM], tlx[NM], tly[NM];
#pragma unroll
    for (int m = 0; m < NM; m++) {
        float x0 = b0[m * 100], y0 = b0[m * 100 + 1];
        float dx = x0 - g0.x, dy = y0 - g0.y;
        float dsum = sqrt_ap(fmaf(dx, dx, dy * dy));
        float x1v = 0.f, y1v = 0.f;
        if (has2) {
            x1v = b1[m * 100]; y1v = b1[m * 100 + 1];
            float ex = x1v - g1.x, ey = y1v - g1.y;
            dsum += sqrt_ap(fmaf(ex, ex, ey * ey));
        }
#pragma unroll
        for (int o = 16; o; o >>= 1) dsum += __shfl_xor_sync(FULL, dsum, o);
        dist[m] = dsum;                        // sum over t (argmin-invariant scale)
        tlx[m] = __shfl_sync(FULL, x1v, 17);   // traj[m][49] lives on lane 17
        tly[m] = __shfl_sync(FULL, y1v, 17);
    }
    float refx = __shfl_sync(FULL, g1.x, 17);  // path_gt[49]
    float refy = __shfl_sync(FULL, g1.y, 17);
    float rn = sqrt_ap(fmaf(refx, refx, refy * refy));
    bool ref_nan = isnan(refx) || isnan(refy);

    // eligible  <=>  angle <= 5deg  <=>  dot >= cos(5deg)*nprod  (nprod>0, no NaN)
    const float COS5 = 0.99619469809174553f;
    const float INF = __int_as_float(0x7f800000);
    float bestKey = INF;
    int best = 0;
    bool any = false;
#pragma unroll
    for (int m = 0; m < NM; m++) {
        float tn = sqrt_ap(fmaf(tlx[m], tlx[m], tly[m] * tly[m]));
        float nprod = rn * tn;
        float dot = fmaf(refx, tlx[m], refy * tly[m]);
        bool nanm = ref_nan || isnan(tlx[m]) || isnan(tly[m]);
        bool elig;
        if (nanm)               elig = false;          // angle := 180 - eps
        else if (nprod == 0.f)  elig = true;           // angle := 0
        else                    elig = (dot >= COS5 * nprod);
        any |= elig;
        float key = elig ? dist[m] : INF;
        if (key < bestKey) { bestKey = key; best = m; }  // strict < => first-min like argmin
    }
    if (!any) best = threefry_mod5((uint32_t)s);

    // ---- deferred huber: only the winning mode (L1-hot reload, warp-uniform offset) ----
    const float* c0 = b0 + best * 100;
    const float* c1 = b1 + best * 100;
    float rsum = huber(c0[0] - g0.x) + huber(c0[1] - g0.y);
    if (has2) rsum += huber(c1[0] - g1.x) + huber(c1[1] - g1.y);
#pragma unroll
    for (int o = 16; o; o >>= 1) rsum += __shfl_xor_sync(FULL, rsum, o);

    // cross-entropy via log_softmax over 5 logits; octet butterfly (each octet self-contained)
    float pr = (lane < NM) ? tp[500 + lane] : -INF;
    float mx = pr;
#pragma unroll
    for (int o = 4; o; o >>= 1) mx = fmaxf(mx, __shfl_xor_sync(FULL, mx, o));
    float e = (lane < NM) ? __expf(pr - mx) : 0.f;
#pragma unroll
    for (int o = 4; o; o >>= 1) e += __shfl_xor_sync(FULL, e, o);
    float pbest = __shfl_sync(FULL, pr, best);

    if (lane == 0) {
        float ce = (mx + __logf(e)) - pbest;
        float p = cr_pred[s], y = cr_gt[s];
        float lp  = fmaxf(__logf(p), -100.0f);
        float l1p = fmaxf(log1pf(-p), -100.0f);
        float bce = -(y * lp + (1.0f - y) * l1p);
        warp_sums[w] = ce + rsum * 0.01f + bce;        // /100 = mean over (50,2)
    }
    __syncthreads();
    if (threadIdx.x == 0) {
        float t = 0.f;
#pragma unroll
        for (int i = 0; i < WPB; i++) t += warp_sums[i];
        g_partials[blockIdx.x] = t;
    }
}

__global__ void __launch_bounds__(1024) combo_reduce(float* __restrict__ out) {
    __shared__ float sm[32];
    const unsigned FULL = 0xffffffffu;
    int lane = threadIdx.x & 31;
    int wid = threadIdx.x >> 5;
    // 8192 floats = 2048 float4; 1024 threads -> 2 float4 each, fixed order
    const float4* p4 = (const float4*)g_partials;
    float4 a = p4[threadIdx.x];
    float4 b = p4[threadIdx.x + 1024];
    float t = ((a.x + a.y) + (a.z + a.w)) + ((b.x + b.y) + (b.z + b.w));
#pragma unroll
    for (int o = 16; o; o >>= 1) t += __shfl_xor_sync(FULL, t, o);
    if (lane == 0) sm[wid] = t;
    __syncthreads();
    if (wid == 0) {
        float v = sm[lane];
#pragma unroll
        for (int o = 16; o; o >>= 1) v += __shfl_xor_sync(FULL, v, o);
        if (lane == 0) out[0] = v * (1.0f / (float)B_SZ);
    }
}

extern "C" void kernel_launch(void* const* d_in, const int* in_sizes, int n_in,
                              void* d_out, int out_size) {
    const float* path_pred = (const float*)d_in[0];
    const float* path_gt   = (const float*)d_in[1];
    const float* cr_pred   = (const float*)d_in[2];
    const float* cr_gt     = (const float*)d_in[3];
    // d_in[4] = log_vars (unused by the reference's returned value)
    combo_main<<<NBLOCKS, 32 * WPB>>>(path_pred, path_gt, cr_pred, cr_gt);
    combo_reduce<<<1, 1024>>>((float*)d_out);
}

// round 5
// speedup vs baseline: 1.2157x; 1.0506x over previous
#include <cuda_runtime.h>
#include <stdint.h>

#define B_SZ 65536
#define NM 5
#define WPB 8
#define NBLOCKS (B_SZ / WPB)  // 8192

__device__ float g_partials[NBLOCKS];
__device__ unsigned g_count;   // zero-init; self-resets every launch

__device__ __forceinline__ float sqrt_ap(float x) {
    float r;
    asm("sqrt.approx.f32 %0, %1;" : "=f"(r) : "f"(x));
    return r;
}

// Smooth-L1 (huber, delta=1): ad<1 ? 0.5 d^2 : ad-0.5 == t*(ad - 0.5t), t=min(ad,1)
__device__ __forceinline__ float huber(float d) {
    float ad = fabsf(d);
    float t = fminf(ad, 1.0f);
    return t * fmaf(-0.5f, t, ad);
}

__device__ __forceinline__ uint32_t rotl32(uint32_t x, uint32_t d) {
    return __funnelshift_l(x, x, d);
}

// JAX partitionable ThreeFry-2x32: key=(0,42), counter=(0,i); randint(0,5) -> (x0^x1) % 5
__device__ __forceinline__ int threefry_mod5(uint32_t i) {
    const uint32_t k0 = 0u, k1 = 42u;
    const uint32_t k2 = k0 ^ k1 ^ 0x1BD11BDAu;
    uint32_t x0 = k0;
    uint32_t x1 = i + k1;
#define TF4(r0, r1, r2, r3)                           \
    x0 += x1; x1 = rotl32(x1, r0); x1 ^= x0;          \
    x0 += x1; x1 = rotl32(x1, r1); x1 ^= x0;          \
    x0 += x1; x1 = rotl32(x1, r2); x1 ^= x0;          \
    x0 += x1; x1 = rotl32(x1, r3); x1 ^= x0;
    TF4(13, 15, 26, 6)   x0 += k1; x1 += k2 + 1u;
    TF4(17, 29, 16, 24)  x0 += k2; x1 += k0 + 2u;
    TF4(13, 15, 26, 6)   x0 += k0; x1 += k1 + 3u;
    TF4(17, 29, 16, 24)  x0 += k1; x1 += k2 + 4u;
    TF4(13, 15, 26, 6)   x0 += k2; x1 += k0 + 5u;
#undef TF4
    return (int)((x0 ^ x1) % 5u);
}

__global__ void __launch_bounds__(32 * WPB)
combo_fused(const float* __restrict__ path_pred,
            const float* __restrict__ path_gt,
            const float* __restrict__ cr_pred,
            const float* __restrict__ cr_gt,
            float* __restrict__ out) {
    __shared__ float warp_sums[WPB];
    __shared__ bool  is_last;
    const unsigned FULL = 0xffffffffu;
    int lane = threadIdx.x & 31;
    int w = threadIdx.x >> 5;
    int s = blockIdx.x * WPB + w;

    const float* tp = path_pred + (size_t)s * 505;                   // 5*50*2 traj + 5 probs
    const float2* gt2 = (const float2*)(path_gt + (size_t)s * 100);  // 400B rows: 8B aligned

    // hoist the BCE inputs: overlap their DRAM latency with the mode loop
    float crp = 0.f, cry = 0.f;
    if (lane == 0) { crp = cr_pred[s]; cry = cr_gt[s]; }

    // lane handles t = lane (always) and t = 32+lane (lane < 18)
    float2 g0 = gt2[lane];
    bool has2 = (lane < 18);
    float2 g1 = make_float2(0.f, 0.f);
    if (has2) g1 = gt2[32 + lane];

    const float* b0 = tp + 2 * lane;           // scalar loads: 505-float rows, odd alignment
    const float* b1 = tp + 2 * (32 + lane);

    // per-lane eligibility state (only lane 17's result is used; broadcast once)
    float rn = sqrt_ap(fmaf(g1.x, g1.x, g1.y * g1.y));
    bool ref_nan = isnan(g1.x) || isnan(g1.y);
    const float COS5 = 0.99619469809174553f;
    unsigned emask = 0;

    // ---- main loop: distances + per-lane eligibility bits ----
    float dist[NM];
#pragma unroll
    for (int m = 0; m < NM; m++) {
        float x0 = b0[m * 100], y0 = b0[m * 100 + 1];
        float dx = x0 - g0.x, dy = y0 - g0.y;
        float dsum = sqrt_ap(fmaf(dx, dx, dy * dy));
        float x1v = 0.f, y1v = 0.f;
        if (has2) {
            x1v = b1[m * 100]; y1v = b1[m * 100 + 1];
            float ex = x1v - g1.x, ey = y1v - g1.y;
            dsum += sqrt_ap(fmaf(ex, ex, ey * ey));
        }
#pragma unroll
        for (int o = 16; o; o >>= 1) dsum += __shfl_xor_sync(FULL, dsum, o);
        dist[m] = dsum;                        // sum over t (argmin-invariant scale)

        // eligibility on each lane with its own (x1v,y1v); lane 17 = traj[m][49]
        float tn = sqrt_ap(fmaf(x1v, x1v, y1v * y1v));
        float nprod = rn * tn;
        float dot = fmaf(g1.x, x1v, g1.y * y1v);
        bool nanm = ref_nan || isnan(x1v) || isnan(y1v);
        bool elig;
        if (nanm)               elig = false;          // angle := 180 - eps
        else if (nprod == 0.f)  elig = true;           // angle := 0
        else                    elig = (dot >= COS5 * nprod);
        emask |= (elig ? 1u : 0u) << m;
    }
    emask = __shfl_sync(FULL, emask, 17);              // lane 17 holds the true mask

    const float INF = __int_as_float(0x7f800000);
    float bestKey = INF;
    int best = 0;
#pragma unroll
    for (int m = 0; m < NM; m++) {
        float key = (emask >> m & 1u) ? dist[m] : INF;
        if (key < bestKey) { bestKey = key; best = m; }  // strict < => first-min like argmin
    }
    if (emask == 0u) best = threefry_mod5((uint32_t)s);

    // ---- deferred huber: only the winning mode (L1-hot reload, warp-uniform offset) ----
    const float* c0 = b0 + best * 100;
    const float* c1 = b1 + best * 100;
    float rsum = huber(c0[0] - g0.x) + huber(c0[1] - g0.y);
    if (has2) rsum += huber(c1[0] - g1.x) + huber(c1[1] - g1.y);
#pragma unroll
    for (int o = 16; o; o >>= 1) rsum += __shfl_xor_sync(FULL, rsum, o);

    // cross-entropy via log_softmax over 5 logits; octet butterfly (each octet self-contained)
    float pr = (lane < NM) ? tp[500 + lane] : -INF;
    float mx = pr;
#pragma unroll
    for (int o = 4; o; o >>= 1) mx = fmaxf(mx, __shfl_xor_sync(FULL, mx, o));
    float e = (lane < NM) ? __expf(pr - mx) : 0.f;
#pragma unroll
    for (int o = 4; o; o >>= 1) e += __shfl_xor_sync(FULL, e, o);
    float pbest = __shfl_sync(FULL, pr, best);

    if (lane == 0) {
        float ce = (mx + __logf(e)) - pbest;
        float lp  = fmaxf(__logf(crp), -100.0f);
        float l1p = fmaxf(log1pf(-crp), -100.0f);
        float bce = -(cry * lp + (1.0f - cry) * l1p);
        warp_sums[w] = ce + rsum * 0.01f + bce;        // /100 = mean over (50,2)
    }
    __syncthreads();
    if (threadIdx.x == 0) {
        float t = 0.f;
#pragma unroll
        for (int i = 0; i < WPB; i++) t += warp_sums[i];
        g_partials[blockIdx.x] = t;
        __threadfence();
        unsigned done = atomicAdd(&g_count, 1u);
        is_last = (done == NBLOCKS - 1);
    }
    __syncthreads();

    if (is_last) {
        // deterministic finalize: 256 threads, 8 float4 each in fixed order, fixed tree
        __shared__ float sm[32];
        const float4* p4 = (const float4*)g_partials;   // 2048 float4, L2-hot
        float t = 0.f;
#pragma unroll
        for (int i = 0; i < 8; i++) {
            float4 a = p4[threadIdx.x + i * 256];
            t += ((a.x + a.y) + (a.z + a.w));
        }
#pragma unroll
        for (int o = 16; o; o >>= 1) t += __shfl_xor_sync(FULL, t, o);
        if (lane == 0) sm[w] = t;
        __syncthreads();
        if (w == 0) {
            float v = (lane < WPB) ? sm[lane] : 0.f;
#pragma unroll
            for (int o = 4; o; o >>= 1) v += __shfl_xor_sync(FULL, v, o);
            if (lane == 0) {
                out[0] = v * (1.0f / (float)B_SZ);
                g_count = 0;                           // reset for next graph replay
            }
        }
    }
}

extern "C" void kernel_launch(void* const* d_in, const int* in_sizes, int n_in,
                              void* d_out, int out_size) {
    const float* path_pred = (const float*)d_in[0];
    const float* path_gt   = (const float*)d_in[1];
    const float* cr_pred   = (const float*)d_in[2];
    const float* cr_gt     = (const float*)d_in[3];
    // d_in[4] = log_vars (unused by the reference's returned value)
    combo_fused<<<NBLOCKS, 32 * WPB>>>(path_pred, path_gt, cr_pred, cr_gt, (float*)d_out);
}

// round 6
// speedup vs baseline: 1.7983x; 1.4792x over previous
#include <cuda_runtime.h>
#include <stdint.h>

#define B_SZ 65536
#define NM 5
#define WPB 8
#define NBLOCKS (B_SZ / WPB)  // 8192

__device__ float g_partials[NBLOCKS];
__device__ unsigned g_count;   // zero-init; self-resets every launch

__device__ __forceinline__ float sqrt_ap(float x) {
    float r;
    asm("sqrt.approx.f32 %0, %1;" : "=f"(r) : "f"(x));
    return r;
}

// Smooth-L1 (huber, delta=1): ad<1 ? 0.5 d^2 : ad-0.5 == t*(ad - 0.5t), t=min(ad,1)
__device__ __forceinline__ float huber(float d) {
    float ad = fabsf(d);
    float t = fminf(ad, 1.0f);
    return t * fmaf(-0.5f, t, ad);
}

__device__ __forceinline__ uint32_t rotl32(uint32_t x, uint32_t d) {
    return __funnelshift_l(x, x, d);
}

// JAX partitionable ThreeFry-2x32: key=(0,42), counter=(0,i); randint(0,5) -> (x0^x1) % 5
__device__ __forceinline__ int threefry_mod5(uint32_t i) {
    const uint32_t k0 = 0u, k1 = 42u;
    const uint32_t k2 = k0 ^ k1 ^ 0x1BD11BDAu;
    uint32_t x0 = k0;
    uint32_t x1 = i + k1;
#define TF4(r0, r1, r2, r3)                           \
    x0 += x1; x1 = rotl32(x1, r0); x1 ^= x0;          \
    x0 += x1; x1 = rotl32(x1, r1); x1 ^= x0;          \
    x0 += x1; x1 = rotl32(x1, r2); x1 ^= x0;          \
    x0 += x1; x1 = rotl32(x1, r3); x1 ^= x0;
    TF4(13, 15, 26, 6)   x0 += k1; x1 += k2 + 1u;
    TF4(17, 29, 16, 24)  x0 += k2; x1 += k0 + 2u;
    TF4(13, 15, 26, 6)   x0 += k0; x1 += k1 + 3u;
    TF4(17, 29, 16, 24)  x0 += k1; x1 += k2 + 4u;
    TF4(13, 15, 26, 6)   x0 += k2; x1 += k0 + 5u;
#undef TF4
    return (int)((x0 ^ x1) % 5u);
}

__global__ void __launch_bounds__(32 * WPB)
combo_fused(const float* __restrict__ path_pred,
            const float* __restrict__ path_gt,
            const float* __restrict__ cr_pred,
            const float* __restrict__ cr_gt,
            float* __restrict__ out) {
    __shared__ float warp_sums[WPB];
    __shared__ int   s_rand[WPB];
    __shared__ bool  is_last;
    const unsigned FULL = 0xffffffffu;
    int lane = threadIdx.x & 31;
    int w = threadIdx.x >> 5;
    int s = blockIdx.x * WPB + w;

    // ThreeFry for all 8 samples of this block, computed once in parallel lanes
    if (threadIdx.x < WPB)
        s_rand[threadIdx.x] = threefry_mod5((uint32_t)(blockIdx.x * WPB + threadIdx.x));

    const float* tp = path_pred + (size_t)s * 505;                   // 5*50*2 traj + 5 probs
    const float2* gt2 = (const float2*)(path_gt + (size_t)s * 100);  // 400B rows: 8B aligned

    // hoist the BCE inputs: overlap their DRAM latency with everything else
    float crp = 0.f, cry = 0.f;
    if (lane == 0) { crp = cr_pred[s]; cry = cr_gt[s]; }

    // lane handles t = lane (always) and t = 32+lane (lane < 18)
    float2 g0 = gt2[lane];
    bool has2 = (lane < 18);
    float2 g1 = make_float2(0.f, 0.f);
    if (has2) g1 = gt2[32 + lane];

    // ---- eligibility first: only last points are needed ----
    float2 ref = gt2[49];                       // uniform address -> broadcast load
    float rn = sqrt_ap(fmaf(ref.x, ref.x, ref.y * ref.y));
    bool ref_nan = isnan(ref.x) || isnan(ref.y);
    const float COS5 = 0.99619469809174553f;

    bool elig = false;
    if (lane < NM) {                            // mode = lane
        float ex = tp[lane * 100 + 98];
        float ey = tp[lane * 100 + 99];
        float tn = sqrt_ap(fmaf(ex, ex, ey * ey));
        float nprod = rn * tn;
        float dot = fmaf(ref.x, ex, ref.y * ey);
        bool nanm = ref_nan || isnan(ex) || isnan(ey);
        if (nanm)               elig = false;   // angle := 180 - eps
        else if (nprod == 0.f)  elig = true;    // angle := 0
        else                    elig = (dot >= COS5 * nprod);
    }
    unsigned emask = __ballot_sync(FULL, elig); // bits 0..4 = modes

    __syncthreads();                            // s_rand ready

    const float INF = __int_as_float(0x7f800000);
    const float* b0 = tp + 2 * lane;            // scalar: 505-float rows, odd alignment
    const float* b1 = tp + 2 * (32 + lane);

    int best;
    if (emask) {
        // ---- heavy path (~13%): distances for eligible modes only ----
        float bestKey = INF;
        best = 0;
#pragma unroll
        for (int m = 0; m < NM; m++) {
            if (emask >> m & 1u) {              // warp-uniform
                float x0 = b0[m * 100], y0 = b0[m * 100 + 1];
                float dx = x0 - g0.x, dy = y0 - g0.y;
                float dsum = sqrt_ap(fmaf(dx, dx, dy * dy));
                if (has2) {
                    float ex = b1[m * 100] - g1.x, ey = b1[m * 100 + 1] - g1.y;
                    dsum += sqrt_ap(fmaf(ex, ex, ey * ey));
                }
#pragma unroll
                for (int o = 16; o; o >>= 1) dsum += __shfl_xor_sync(FULL, dsum, o);
                if (dsum < bestKey) { bestKey = dsum; best = m; }  // strict < = first-min
            }
        }
    } else {
        best = s_rand[w];                       // ~87%: traj dist loads never issued
    }

    // ---- huber: only the winning mode (warp-uniform offset) ----
    const float* c0 = b0 + best * 100;
    const float* c1 = b1 + best * 100;
    float rsum = huber(c0[0] - g0.x) + huber(c0[1] - g0.y);
    if (has2) rsum += huber(c1[0] - g1.x) + huber(c1[1] - g1.y);
#pragma unroll
    for (int o = 16; o; o >>= 1) rsum += __shfl_xor_sync(FULL, rsum, o);

    // cross-entropy via log_softmax over 5 logits; octet butterfly (each octet self-contained)
    float pr = (lane < NM) ? tp[500 + lane] : -INF;
    float mx = pr;
#pragma unroll
    for (int o = 4; o; o >>= 1) mx = fmaxf(mx, __shfl_xor_sync(FULL, mx, o));
    float e = (lane < NM) ? __expf(pr - mx) : 0.f;
#pragma unroll
    for (int o = 4; o; o >>= 1) e += __shfl_xor_sync(FULL, e, o);
    float pbest = __shfl_sync(FULL, pr, best);

    if (lane == 0) {
        float ce = (mx + __logf(e)) - pbest;
        float lp  = fmaxf(__logf(crp), -100.0f);
        float l1p = fmaxf(log1pf(-crp), -100.0f);
        float bce = -(cry * lp + (1.0f - cry) * l1p);
        warp_sums[w] = ce + rsum * 0.01f + bce;        // /100 = mean over (50,2)
    }
    __syncthreads();
    if (threadIdx.x == 0) {
        float t = 0.f;
#pragma unroll
        for (int i = 0; i < WPB; i++) t += warp_sums[i];
        g_partials[blockIdx.x] = t;
        __threadfence();
        unsigned done = atomicAdd(&g_count, 1u);
        is_last = (done == NBLOCKS - 1);
    }
    __syncthreads();

    if (is_last) {
        // deterministic finalize: 256 threads, 8 float4 each in fixed order, fixed tree
        __shared__ float sm[32];
        const float4* p4 = (const float4*)g_partials;   // 2048 float4, L2-hot
        float t = 0.f;
#pragma unroll
        for (int i = 0; i < 8; i++) {
            float4 a = p4[threadIdx.x + i * 256];
            t += ((a.x + a.y) + (a.z + a.w));
        }
#pragma unroll
        for (int o = 16; o; o >>= 1) t += __shfl_xor_sync(FULL, t, o);
        if (lane == 0) sm[w] = t;
        __syncthreads();
        if (w == 0) {
            float v = (lane < WPB) ? sm[lane] : 0.f;
#pragma unroll
            for (int o = 4; o; o >>= 1) v += __shfl_xor_sync(FULL, v, o);
            if (lane == 0) {
                out[0] = v * (1.0f / (float)B_SZ);
                g_count = 0;                           // reset for next graph replay
            }
        }
    }
}

extern "C" void kernel_launch(void* const* d_in, const int* in_sizes, int n_in,
                              void* d_out, int out_size) {
    const float* path_pred = (const float*)d_in[0];
    const float* path_gt   = (const float*)d_in[1];
    const float* cr_pred   = (const float*)d_in[2];
    const float* cr_gt     = (const float*)d_in[3];
    // d_in[4] = log_vars (unused by the reference's returned value)
    combo_fused<<<NBLOCKS, 32 * WPB>>>(path_pred, path_gt, cr_pred, cr_gt, (float*)d_out);
}

// round 7
// speedup vs baseline: 1.8990x; 1.0560x over previous
#include <cuda_runtime.h>
#include <stdint.h>

#define B_SZ 65536
#define NM 5
#define WPB 8
#define NBLOCKS (B_SZ / WPB)  // 8192

__device__ float g_partials[NBLOCKS];
__device__ unsigned g_count;   // zero-init; self-resets every launch

__device__ __forceinline__ float sqrt_ap(float x) {
    float r;
    asm("sqrt.approx.f32 %0, %1;" : "=f"(r) : "f"(x));
    return r;
}

// Smooth-L1 (huber, delta=1): ad<1 ? 0.5 d^2 : ad-0.5 == t*(ad - 0.5t), t=min(ad,1)
__device__ __forceinline__ float huber(float d) {
    float ad = fabsf(d);
    float t = fminf(ad, 1.0f);
    return t * fmaf(-0.5f, t, ad);
}

__device__ __forceinline__ uint32_t rotl32(uint32_t x, uint32_t d) {
    return __funnelshift_l(x, x, d);
}

// JAX partitionable ThreeFry-2x32: key=(0,42), counter=(0,i); randint(0,5) -> (x0^x1) % 5
__device__ __forceinline__ int threefry_mod5(uint32_t i) {
    const uint32_t k0 = 0u, k1 = 42u;
    const uint32_t k2 = k0 ^ k1 ^ 0x1BD11BDAu;
    uint32_t x0 = k0;
    uint32_t x1 = i + k1;
#define TF4(r0, r1, r2, r3)                           \
    x0 += x1; x1 = rotl32(x1, r0); x1 ^= x0;          \
    x0 += x1; x1 = rotl32(x1, r1); x1 ^= x0;          \
    x0 += x1; x1 = rotl32(x1, r2); x1 ^= x0;          \
    x0 += x1; x1 = rotl32(x1, r3); x1 ^= x0;
    TF4(13, 15, 26, 6)   x0 += k1; x1 += k2 + 1u;
    TF4(17, 29, 16, 24)  x0 += k2; x1 += k0 + 2u;
    TF4(13, 15, 26, 6)   x0 += k0; x1 += k1 + 3u;
    TF4(17, 29, 16, 24)  x0 += k1; x1 += k2 + 4u;
    TF4(13, 15, 26, 6)   x0 += k2; x1 += k0 + 5u;
#undef TF4
    return (int)((x0 ^ x1) % 5u);
}

__global__ void __launch_bounds__(32 * WPB)
combo_fused(const float* __restrict__ path_pred,
            const float* __restrict__ path_gt,
            const float* __restrict__ cr_pred,
            const float* __restrict__ cr_gt,
            float* __restrict__ out) {
    __shared__ float warp_sums[WPB];
    __shared__ int   s_rand[WPB];
    __shared__ bool  is_last;
    const unsigned FULL = 0xffffffffu;
    int lane = threadIdx.x & 31;
    int w = threadIdx.x >> 5;
    int s = blockIdx.x * WPB + w;

    const float* tp = path_pred + (size_t)s * 505;                   // 5*50*2 traj + 5 probs
    const float2* gt2 = (const float2*)(path_gt + (size_t)s * 100);  // 400B rows: 8B aligned
    const float INF = __int_as_float(0x7f800000);

    // ---- batch 1: all unconditional loads, issued before any dependent work ----
    float2 g0 = gt2[lane];                      // t = lane
    bool has2 = (lane < 18);
    float2 g1 = make_float2(0.f, 0.f);
    if (has2) g1 = gt2[32 + lane];              // t = 32+lane
    float2 ref = gt2[49];                       // uniform -> broadcast load
    float ex_e = 0.f, ey_e = 0.f;
    if (lane < NM) {                            // eligibility last-points, mode = lane
        ex_e = tp[lane * 100 + 98];
        ey_e = tp[lane * 100 + 99];
    }
    float pr = (lane < NM) ? tp[500 + lane] : -INF;   // mode logits
    float crp = 0.f, cry = 0.f;
    if (lane == 0) { crp = cr_pred[s]; cry = cr_gt[s]; }

    // ---- ALU while batch 1 is in flight: ThreeFry for the 8 block samples ----
    if (threadIdx.x < WPB)
        s_rand[threadIdx.x] = threefry_mod5((uint32_t)(blockIdx.x * WPB + threadIdx.x));
    __syncthreads();                            // early: warps arrive nearly together
    int rnd = s_rand[w];

    // ---- batch 2: speculative huber loads for the rand mode (87% the winner) ----
    const float* b0 = tp + 2 * lane;            // scalar: 505-float rows, odd alignment
    const float* b1 = tp + 2 * (32 + lane);
    const float* r0 = b0 + rnd * 100;
    const float* r1 = b1 + rnd * 100;
    float sx0 = r0[0], sy0 = r0[1];
    float sx1 = 0.f, sy1 = 0.f;
    if (has2) { sx1 = r1[0]; sy1 = r1[1]; }

    // ---- eligibility from batch-1 registers ----
    float rn = sqrt_ap(fmaf(ref.x, ref.x, ref.y * ref.y));
    bool ref_nan = isnan(ref.x) || isnan(ref.y);
    const float COS5 = 0.99619469809174553f;
    bool elig = false;
    if (lane < NM) {
        float tn = sqrt_ap(fmaf(ex_e, ex_e, ey_e * ey_e));
        float nprod = rn * tn;
        float dot = fmaf(ref.x, ex_e, ref.y * ey_e);
        bool nanm = ref_nan || isnan(ex_e) || isnan(ey_e);
        if (nanm)               elig = false;   // angle := 180 - eps
        else if (nprod == 0.f)  elig = true;    // angle := 0
        else                    elig = (dot >= COS5 * nprod);
    }
    unsigned emask = __ballot_sync(FULL, elig); // bits 0..4 = modes

    int best;
    float rsum;
    if (emask) {
        // ---- heavy path (~13%): distances for eligible modes only ----
        float bestKey = INF;
        best = 0;
#pragma unroll
        for (int m = 0; m < NM; m++) {
            if (emask >> m & 1u) {              // warp-uniform
                float x0 = b0[m * 100], y0 = b0[m * 100 + 1];
                float dx = x0 - g0.x, dy = y0 - g0.y;
                float dsum = sqrt_ap(fmaf(dx, dx, dy * dy));
                if (has2) {
                    float ex = b1[m * 100] - g1.x, ey = b1[m * 100 + 1] - g1.y;
                    dsum += sqrt_ap(fmaf(ex, ex, ey * ey));
                }
#pragma unroll
                for (int o = 16; o; o >>= 1) dsum += __shfl_xor_sync(FULL, dsum, o);
                if (dsum < bestKey) { bestKey = dsum; best = m; }  // strict < = first-min
            }
        }
        const float* c0 = b0 + best * 100;      // reload true winner (likely L1/L2-hot)
        const float* c1 = b1 + best * 100;
        rsum = huber(c0[0] - g0.x) + huber(c0[1] - g0.y);
        if (has2) rsum += huber(c1[0] - g1.x) + huber(c1[1] - g1.y);
    } else {
        // ---- fast path (~87%): operands already in registers, zero extra trips ----
        best = rnd;
        rsum = huber(sx0 - g0.x) + huber(sy0 - g0.y);
        if (has2) rsum += huber(sx1 - g1.x) + huber(sy1 - g1.y);
    }
#pragma unroll
    for (int o = 16; o; o >>= 1) rsum += __shfl_xor_sync(FULL, rsum, o);

    // cross-entropy via log_softmax over 5 logits; octet butterfly (each octet self-contained)
    float mx = pr;
#pragma unroll
    for (int o = 4; o; o >>= 1) mx = fmaxf(mx, __shfl_xor_sync(FULL, mx, o));
    float e = (lane < NM) ? __expf(pr - mx) : 0.f;
#pragma unroll
    for (int o = 4; o; o >>= 1) e += __shfl_xor_sync(FULL, e, o);
    float pbest = __shfl_sync(FULL, pr, best);

    if (lane == 0) {
        float ce = (mx + __logf(e)) - pbest;
        float lp  = fmaxf(__logf(crp), -100.0f);
        float l1p = fmaxf(log1pf(-crp), -100.0f);
        float bce = -(cry * lp + (1.0f - cry) * l1p);
        warp_sums[w] = ce + rsum * 0.01f + bce;        // /100 = mean over (50,2)
    }
    __syncthreads();
    if (threadIdx.x == 0) {
        float t = 0.f;
#pragma unroll
        for (int i = 0; i < WPB; i++) t += warp_sums[i];
        g_partials[blockIdx.x] = t;
        __threadfence();
        unsigned done = atomicAdd(&g_count, 1u);
        is_last = (done == NBLOCKS - 1);
    }
    __syncthreads();

    if (is_last) {
        // deterministic finalize: 256 threads, 8 float4 each in fixed order, fixed tree
        __shared__ float sm[32];
        const float4* p4 = (const float4*)g_partials;   // 2048 float4, L2-hot
        float t = 0.f;
#pragma unroll
        for (int i = 0; i < 8; i++) {
            float4 a = p4[threadIdx.x + i * 256];
            t += ((a.x + a.y) + (a.z + a.w));
        }
#pragma unroll
        for (int o = 16; o; o >>= 1) t += __shfl_xor_sync(FULL, t, o);
        if (lane == 0) sm[w] = t;
        __syncthreads();
        if (w == 0) {
            float v = (lane < WPB) ? sm[lane] : 0.f;
#pragma unroll
            for (int o = 4; o; o >>= 1) v += __shfl_xor_sync(FULL, v, o);
            if (lane == 0) {
                out[0] = v * (1.0f / (float)B_SZ);
                g_count = 0;                           // reset for next graph replay
            }
        }
    }
}

extern "C" void kernel_launch(void* const* d_in, const int* in_sizes, int n_in,
                              void* d_out, int out_size) {
    const float* path_pred = (const float*)d_in[0];
    const float* path_gt   = (const float*)d_in[1];
    const float* cr_pred   = (const float*)d_in[2];
    const float* cr_gt     = (const float*)d_in[3];
    // d_in[4] = log_vars (unused by the reference's returned value)
    combo_fused<<<NBLOCKS, 32 * WPB>>>(path_pred, path_gt, cr_pred, cr_gt, (float*)d_out);
}

// round 8
// speedup vs baseline: 2.0116x; 1.0593x over previous
#include <cuda_runtime.h>
#include <stdint.h>

#define B_SZ 65536
#define NM 5
#define WPB 8
#define SPB (WPB * 2)            // 16 samples per block (2 per warp)
#define NBLOCKS (B_SZ / SPB)     // 4096

__device__ float g_partials[NBLOCKS];
__device__ unsigned g_count;     // zero-init; self-resets every launch

__device__ __forceinline__ float sqrt_ap(float x) {
    float r;
    asm("sqrt.approx.f32 %0, %1;" : "=f"(r) : "f"(x));
    return r;
}

// Smooth-L1 (huber, delta=1): ad<1 ? 0.5 d^2 : ad-0.5 == t*(ad - 0.5t), t=min(ad,1)
__device__ __forceinline__ float huber(float d) {
    float ad = fabsf(d);
    float t = fminf(ad, 1.0f);
    return t * fmaf(-0.5f, t, ad);
}

__device__ __forceinline__ uint32_t rotl32(uint32_t x, uint32_t d) {
    return __funnelshift_l(x, x, d);
}

// JAX partitionable ThreeFry-2x32: key=(0,42), counter=(0,i); randint(0,5) -> (x0^x1) % 5
__device__ __forceinline__ int threefry_mod5(uint32_t i) {
    const uint32_t k0 = 0u, k1 = 42u;
    const uint32_t k2 = k0 ^ k1 ^ 0x1BD11BDAu;
    uint32_t x0 = k0;
    uint32_t x1 = i + k1;
#define TF4(r0, r1, r2, r3)                           \
    x0 += x1; x1 = rotl32(x1, r0); x1 ^= x0;          \
    x0 += x1; x1 = rotl32(x1, r1); x1 ^= x0;          \
    x0 += x1; x1 = rotl32(x1, r2); x1 ^= x0;          \
    x0 += x1; x1 = rotl32(x1, r3); x1 ^= x0;
    TF4(13, 15, 26, 6)   x0 += k1; x1 += k2 + 1u;
    TF4(17, 29, 16, 24)  x0 += k2; x1 += k0 + 2u;
    TF4(13, 15, 26, 6)   x0 += k0; x1 += k1 + 3u;
    TF4(17, 29, 16, 24)  x0 += k1; x1 += k2 + 4u;
    TF4(13, 15, 26, 6)   x0 += k2; x1 += k0 + 5u;
#undef TF4
    return (int)((x0 ^ x1) % 5u);
}

// dist-based argmin over eligible modes (heavy path); returns best, sets rsum partial
__device__ __forceinline__ void heavy_best(
    const float* b0, const float* b1, float2 g0, float2 g1, bool has2,
    unsigned emask, unsigned FULL, float INF, int& best, float& rs) {
    float bestKey = INF;
    best = 0;
#pragma unroll
    for (int m = 0; m < NM; m++) {
        if (emask >> m & 1u) {                 // warp-uniform
            float dx = b0[m * 100] - g0.x, dy = b0[m * 100 + 1] - g0.y;
            float dsum = sqrt_ap(fmaf(dx, dx, dy * dy));
            if (has2) {
                float ex = b1[m * 100] - g1.x, ey = b1[m * 100 + 1] - g1.y;
                dsum += sqrt_ap(fmaf(ex, ex, ey * ey));
            }
#pragma unroll
            for (int o = 16; o; o >>= 1) dsum += __shfl_xor_sync(FULL, dsum, o);
            if (dsum < bestKey) { bestKey = dsum; best = m; }  // strict < = first-min
        }
    }
    const float* c0 = b0 + best * 100;         // reload true winner (L1/L2-hot)
    const float* c1 = b1 + best * 100;
    rs = huber(c0[0] - g0.x) + huber(c0[1] - g0.y);
    if (has2) rs += huber(c1[0] - g1.x) + huber(c1[1] - g1.y);
}

__global__ void __launch_bounds__(32 * WPB)
combo_fused(const float* __restrict__ path_pred,
            const float* __restrict__ path_gt,
            const float* __restrict__ cr_pred,
            const float* __restrict__ cr_gt,
            float* __restrict__ out) {
    __shared__ float warp_sums[WPB];
    __shared__ int   s_rand[SPB];
    __shared__ bool  is_last;
    const unsigned FULL = 0xffffffffu;
    const float INF = __int_as_float(0x7f800000);
    const float COS5 = 0.99619469809174553f;
    int lane = threadIdx.x & 31;
    int w = threadIdx.x >> 5;
    int sA = blockIdx.x * SPB + 2 * w;
    int sB = sA + 1;

    const float* tpA = path_pred + (size_t)sA * 505;
    const float* tpB = tpA + 505;
    const float2* gtA = (const float2*)(path_gt + (size_t)sA * 100);
    const float2* gtB = gtA + 50;

    // ---- batch 1: all unconditional loads for BOTH samples, back-to-back ----
    bool has2 = (lane < 18);
    float2 g0A = gtA[lane], g0B = gtB[lane];
    float2 g1A = make_float2(0.f, 0.f), g1B = make_float2(0.f, 0.f);
    if (has2) { g1A = gtA[32 + lane]; g1B = gtB[32 + lane]; }
    float2 refA = gtA[49], refB = gtB[49];      // uniform -> broadcast loads
    float exA = 0.f, eyA = 0.f, exB = 0.f, eyB = 0.f;
    if (lane < NM) {                            // eligibility last-points, mode = lane
        exA = tpA[lane * 100 + 98]; eyA = tpA[lane * 100 + 99];
        exB = tpB[lane * 100 + 98]; eyB = tpB[lane * 100 + 99];
    }
    float prA = (lane < NM) ? tpA[500 + lane] : -INF;
    float prB = (lane < NM) ? tpB[500 + lane] : -INF;
    float crpA = 0.f, cryA = 0.f, crpB = 0.f, cryB = 0.f;
    if (lane == 0) {
        crpA = cr_pred[sA]; cryA = cr_gt[sA];
        crpB = cr_pred[sB]; cryB = cr_gt[sB];
    }

    // ---- ALU while batch 1 is in flight: ThreeFry for the 16 block samples ----
    if (threadIdx.x < SPB)
        s_rand[threadIdx.x] = threefry_mod5((uint32_t)(blockIdx.x * SPB + threadIdx.x));
    __syncthreads();
    int rndA = s_rand[2 * w], rndB = s_rand[2 * w + 1];

    // ---- batch 2: speculative huber loads for the rand modes (both samples) ----
    const float* b0A = tpA + 2 * lane; const float* b1A = b0A + 64;
    const float* b0B = tpB + 2 * lane; const float* b1B = b0B + 64;
    const float* r0A = b0A + rndA * 100; const float* r1A = b1A + rndA * 100;
    const float* r0B = b0B + rndB * 100; const float* r1B = b1B + rndB * 100;
    float sx0A = r0A[0], sy0A = r0A[1], sx0B = r0B[0], sy0B = r0B[1];
    float sx1A = 0.f, sy1A = 0.f, sx1B = 0.f, sy1B = 0.f;
    if (has2) { sx1A = r1A[0]; sy1A = r1A[1]; sx1B = r1B[0]; sy1B = r1B[1]; }

    // ---- eligibility for both samples from batch-1 registers ----
    bool eligA = false, eligB = false;
    {
        float rnA = sqrt_ap(fmaf(refA.x, refA.x, refA.y * refA.y));
        float rnB = sqrt_ap(fmaf(refB.x, refB.x, refB.y * refB.y));
        bool rnanA = isnan(refA.x) || isnan(refA.y);
        bool rnanB = isnan(refB.x) || isnan(refB.y);
        if (lane < NM) {
            float tnA = sqrt_ap(fmaf(exA, exA, eyA * eyA));
            float tnB = sqrt_ap(fmaf(exB, exB, eyB * eyB));
            float npA = rnA * tnA, npB = rnB * tnB;
            float dotA = fmaf(refA.x, exA, refA.y * eyA);
            float dotB = fmaf(refB.x, exB, refB.y * eyB);
            bool nanA = rnanA || isnan(exA) || isnan(eyA);
            bool nanB = rnanB || isnan(exB) || isnan(eyB);
            eligA = nanA ? false : (npA == 0.f ? true : (dotA >= COS5 * npA));
            eligB = nanB ? false : (npB == 0.f ? true : (dotB >= COS5 * npB));
        }
    }
    unsigned emA = __ballot_sync(FULL, eligA);  // bits 0..4 = modes
    unsigned emB = __ballot_sync(FULL, eligB);

    // ---- per-sample best + rsum partial (fast path uses speculative registers) ----
    int bestA, bestB;
    float rsA, rsB;
    if (emA) {
        heavy_best(b0A, b1A, g0A, g1A, has2, emA, FULL, INF, bestA, rsA);
    } else {
        bestA = rndA;
        rsA = huber(sx0A - g0A.x) + huber(sy0A - g0A.y);
        if (has2) rsA += huber(sx1A - g1A.x) + huber(sy1A - g1A.y);
    }
    if (emB) {
        heavy_best(b0B, b1B, g0B, g1B, has2, emB, FULL, INF, bestB, rsB);
    } else {
        bestB = rndB;
        rsB = huber(sx0B - g0B.x) + huber(sy0B - g0B.y);
        if (has2) rsB += huber(sx1B - g1B.x) + huber(sy1B - g1B.y);
    }

    // interleaved butterflies: A and B latencies overlap
#pragma unroll
    for (int o = 16; o; o >>= 1) {
        rsA += __shfl_xor_sync(FULL, rsA, o);
        rsB += __shfl_xor_sync(FULL, rsB, o);
    }

    // interleaved log_softmax over 5 logits (octet butterflies)
    float mxA = prA, mxB = prB;
#pragma unroll
    for (int o = 4; o; o >>= 1) {
        mxA = fmaxf(mxA, __shfl_xor_sync(FULL, mxA, o));
        mxB = fmaxf(mxB, __shfl_xor_sync(FULL, mxB, o));
    }
    float eA = (lane < NM) ? __expf(prA - mxA) : 0.f;
    float eB = (lane < NM) ? __expf(prB - mxB) : 0.f;
#pragma unroll
    for (int o = 4; o; o >>= 1) {
        eA += __shfl_xor_sync(FULL, eA, o);
        eB += __shfl_xor_sync(FULL, eB, o);
    }
    float pbA = __shfl_sync(FULL, prA, bestA);
    float pbB = __shfl_sync(FULL, prB, bestB);

    if (lane == 0) {
        float ceA = (mxA + __logf(eA)) - pbA;
        float ceB = (mxB + __logf(eB)) - pbB;
        float lpA  = fmaxf(__logf(crpA), -100.0f);
        float l1pA = fmaxf(log1pf(-crpA), -100.0f);
        float lpB  = fmaxf(__logf(crpB), -100.0f);
        float l1pB = fmaxf(log1pf(-crpB), -100.0f);
        float bceA = -(cryA * lpA + (1.0f - cryA) * l1pA);
        float bceB = -(cryB * lpB + (1.0f - cryB) * l1pB);
        warp_sums[w] = (ceA + rsA * 0.01f + bceA) + (ceB + rsB * 0.01f + bceB);
    }
    __syncthreads();
    if (threadIdx.x == 0) {
        float t = 0.f;
#pragma unroll
        for (int i = 0; i < WPB; i++) t += warp_sums[i];
        g_partials[blockIdx.x] = t;
        __threadfence();
        unsigned done = atomicAdd(&g_count, 1u);
        is_last = (done == NBLOCKS - 1);
    }
    __syncthreads();

    if (is_last) {
        // deterministic finalize: 256 threads, 4 float4 each in fixed order, fixed tree
        __shared__ float sm[32];
        const float4* p4 = (const float4*)g_partials;   // 1024 float4, L2-hot
        float t = 0.f;
#pragma unroll
        for (int i = 0; i < 4; i++) {
            float4 a = p4[threadIdx.x + i * 256];
            t += ((a.x + a.y) + (a.z + a.w));
        }
#pragma unroll
        for (int o = 16; o; o >>= 1) t += __shfl_xor_sync(FULL, t, o);
        if (lane == 0) sm[w] = t;
        __syncthreads();
        if (w == 0) {
            float v = (lane < WPB) ? sm[lane] : 0.f;
#pragma unroll
            for (int o = 4; o; o >>= 1) v += __shfl_xor_sync(FULL, v, o);
            if (lane == 0) {
                out[0] = v * (1.0f / (float)B_SZ);
                g_count = 0;                           // reset for next graph replay
            }
        }
    }
}

extern "C" void kernel_launch(void* const* d_in, const int* in_sizes, int n_in,
                              void* d_out, int out_size) {
    const float* path_pred = (const float*)d_in[0];
    const float* path_gt   = (const float*)d_in[1];
    const float* cr_pred   = (const float*)d_in[2];
    const float* cr_gt     = (const float*)d_in[3];
    // d_in[4] = log_vars (unused by the reference's returned value)
    combo_fused<<<NBLOCKS, 32 * WPB>>>(path_pred, path_gt, cr_pred, cr_gt, (float*)d_out);
}

// round 9
// speedup vs baseline: 2.0425x; 1.0153x over previous
#include <cuda_runtime.h>
#include <stdint.h>

#define B_SZ 65536
#define NM 5
#define WPB 8
#define SPB (WPB * 2)            // 16 samples per block (2 per warp)
#define NBLOCKS (B_SZ / SPB)     // 4096

__device__ float g_partials[NBLOCKS];
__device__ unsigned g_count;     // zero-init; self-resets every launch

__device__ __forceinline__ float sqrt_ap(float x) {
    float r;
    asm("sqrt.approx.f32 %0, %1;" : "=f"(r) : "f"(x));
    return r;
}

// Smooth-L1 (huber, delta=1): ad<1 ? 0.5 d^2 : ad-0.5 == t*(ad - 0.5t), t=min(ad,1)
__device__ __forceinline__ float huber(float d) {
    float ad = fabsf(d);
    float t = fminf(ad, 1.0f);
    return t * fmaf(-0.5f, t, ad);
}

__device__ __forceinline__ uint32_t rotl32(uint32_t x, uint32_t d) {
    return __funnelshift_l(x, x, d);
}

// JAX partitionable ThreeFry-2x32: key=(0,42), counter=(0,i); randint(0,5) -> (x0^x1) % 5
__device__ __forceinline__ int threefry_mod5(uint32_t i) {
    const uint32_t k0 = 0u, k1 = 42u;
    const uint32_t k2 = k0 ^ k1 ^ 0x1BD11BDAu;
    uint32_t x0 = k0;
    uint32_t x1 = i + k1;
#define TF4(r0, r1, r2, r3)                           \
    x0 += x1; x1 = rotl32(x1, r0); x1 ^= x0;          \
    x0 += x1; x1 = rotl32(x1, r1); x1 ^= x0;          \
    x0 += x1; x1 = rotl32(x1, r2); x1 ^= x0;          \
    x0 += x1; x1 = rotl32(x1, r3); x1 ^= x0;
    TF4(13, 15, 26, 6)   x0 += k1; x1 += k2 + 1u;
    TF4(17, 29, 16, 24)  x0 += k2; x1 += k0 + 2u;
    TF4(13, 15, 26, 6)   x0 += k0; x1 += k1 + 3u;
    TF4(17, 29, 16, 24)  x0 += k1; x1 += k2 + 4u;
    TF4(13, 15, 26, 6)   x0 += k2; x1 += k0 + 5u;
#undef TF4
    return (int)((x0 ^ x1) % 5u);
}

// dist-based argmin over eligible modes (heavy path, ~13% of samples)
// b = tp + 2*lane; off = 0 (sample A) or 505 (sample B)
__device__ __forceinline__ void heavy_best(
    const float* __restrict__ b, int off, float2 g0, float2 g1, bool has2,
    unsigned emask, int& best, float& rs) {
    const unsigned FULL = 0xffffffffu;
    const float INF = __int_as_float(0x7f800000);
    float bestKey = INF;
    best = 0;
#pragma unroll
    for (int m = 0; m < NM; m++) {
        if (emask >> m & 1u) {                 // warp-uniform
            int i = off + m * 100;
            float dx = b[i] - g0.x, dy = b[i + 1] - g0.y;
            float dsum = sqrt_ap(fmaf(dx, dx, dy * dy));
            if (has2) {
                float ex = b[i + 64] - g1.x, ey = b[i + 65] - g1.y;
                dsum += sqrt_ap(fmaf(ex, ex, ey * ey));
            }
#pragma unroll
            for (int o = 16; o; o >>= 1) dsum += __shfl_xor_sync(FULL, dsum, o);
            if (dsum < bestKey) { bestKey = dsum; best = m; }  // strict < = first-min
        }
    }
    int c = off + best * 100;                  // reload true winner (L1/L2-hot)
    rs = huber(b[c] - g0.x) + huber(b[c + 1] - g0.y);
    if (has2) rs += huber(b[c + 64] - g1.x) + huber(b[c + 65] - g1.y);
}

__global__ void __launch_bounds__(32 * WPB, 6)
combo_fused(const float* __restrict__ path_pred,
            const float* __restrict__ path_gt,
            const float* __restrict__ cr_pred,
            const float* __restrict__ cr_gt,
            float* __restrict__ out) {
    __shared__ float warp_sums[WPB];
    __shared__ bool  is_last;
    const unsigned FULL = 0xffffffffu;
    const float INF = __int_as_float(0x7f800000);
    const float COS5 = 0.99619469809174553f;
    int lane = threadIdx.x & 31;
    int w = threadIdx.x >> 5;
    int sA = blockIdx.x * SPB + 2 * w;

    const float* tp = path_pred + (size_t)sA * 505;                  // sample A base; B at +505
    const float2* gt = (const float2*)(path_gt + (size_t)sA * 100);  // A rows; B at +50

    // ---- ThreeFry in-warp (pure ALU, no barrier): lane0 -> sA, lane1 -> sB ----
    int tfv = threefry_mod5((uint32_t)(sA + (lane & 1)));
    int rndA = __shfl_sync(FULL, tfv, 0);
    int rndB = __shfl_sync(FULL, tfv, 1);

    // ---- batch 1: all unconditional loads for BOTH samples, back-to-back ----
    bool has2 = (lane < 18);
    float2 g0A = gt[lane],        g0B = gt[50 + lane];
    float2 g1A = make_float2(0.f, 0.f), g1B = make_float2(0.f, 0.f);
    if (has2) { g1A = gt[32 + lane]; g1B = gt[82 + lane]; }
    float2 refA = gt[49], refB = gt[99];        // uniform -> broadcast loads
    float exA = 0.f, eyA = 0.f, exB = 0.f, eyB = 0.f;
    if (lane < NM) {                            // eligibility last-points, mode = lane
        int e = lane * 100 + 98;
        exA = tp[e];       eyA = tp[e + 1];
        exB = tp[e + 505]; eyB = tp[e + 506];
    }
    float prA = (lane < NM) ? tp[500 + lane]  : -INF;
    float prB = (lane < NM) ? tp[1005 + lane] : -INF;
    float crpA = 0.f, cryA = 0.f, crpB = 0.f, cryB = 0.f;
    if (lane == 0) {
        crpA = cr_pred[sA]; cryA = cr_gt[sA];
        crpB = cr_pred[sA + 1]; cryB = cr_gt[sA + 1];
    }

    // ---- batch 2: speculative huber loads for the rand modes (both samples) ----
    const float* b = tp + 2 * lane;             // shared base; B via +505 offsets
    int iA = rndA * 100;
    int iB = 505 + rndB * 100;
    float sx0A = b[iA], sy0A = b[iA + 1], sx0B = b[iB], sy0B = b[iB + 1];
    float sx1A = 0.f, sy1A = 0.f, sx1B = 0.f, sy1B = 0.f;
    if (has2) {
        sx1A = b[iA + 64]; sy1A = b[iA + 65];
        sx1B = b[iB + 64]; sy1B = b[iB + 65];
    }

    // ---- eligibility for both samples from batch-1 registers ----
    bool eligA = false, eligB = false;
    {
        float rnA = sqrt_ap(fmaf(refA.x, refA.x, refA.y * refA.y));
        float rnB = sqrt_ap(fmaf(refB.x, refB.x, refB.y * refB.y));
        bool rnanA = isnan(refA.x) || isnan(refA.y);
        bool rnanB = isnan(refB.x) || isnan(refB.y);
        if (lane < NM) {
            float tnA = sqrt_ap(fmaf(exA, exA, eyA * eyA));
            float tnB = sqrt_ap(fmaf(exB, exB, eyB * eyB));
            float npA = rnA * tnA, npB = rnB * tnB;
            float dotA = fmaf(refA.x, exA, refA.y * eyA);
            float dotB = fmaf(refB.x, exB, refB.y * eyB);
            bool nanA = rnanA || isnan(exA) || isnan(eyA);
            bool nanB = rnanB || isnan(exB) || isnan(eyB);
            eligA = nanA ? false : (npA == 0.f ? true : (dotA >= COS5 * npA));
            eligB = nanB ? false : (npB == 0.f ? true : (dotB >= COS5 * npB));
        }
    }
    unsigned emA = __ballot_sync(FULL, eligA);  // bits 0..4 = modes
    unsigned emB = __ballot_sync(FULL, eligB);

    // ---- per-sample best + rsum partial (fast path uses speculative registers) ----
    int bestA, bestB;
    float rsA, rsB;
    if (emA) {
        heavy_best(b, 0, g0A, g1A, has2, emA, bestA, rsA);
    } else {
        bestA = rndA;
        rsA = huber(sx0A - g0A.x) + huber(sy0A - g0A.y);
        if (has2) rsA += huber(sx1A - g1A.x) + huber(sy1A - g1A.y);
    }
    if (emB) {
        heavy_best(b, 505, g0B, g1B, has2, emB, bestB, rsB);
    } else {
        bestB = rndB;
        rsB = huber(sx0B - g0B.x) + huber(sy0B - g0B.y);
        if (has2) rsB += huber(sx1B - g1B.x) + huber(sy1B - g1B.y);
    }

    // interleaved butterflies: A and B latencies overlap
#pragma unroll
    for (int o = 16; o; o >>= 1) {
        rsA += __shfl_xor_sync(FULL, rsA, o);
        rsB += __shfl_xor_sync(FULL, rsB, o);
    }

    // interleaved log_softmax over 5 logits (octet butterflies)
    float mxA = prA, mxB = prB;
#pragma unroll
    for (int o = 4; o; o >>= 1) {
        mxA = fmaxf(mxA, __shfl_xor_sync(FULL, mxA, o));
        mxB = fmaxf(mxB, __shfl_xor_sync(FULL, mxB, o));
    }
    float eA = (lane < NM) ? __expf(prA - mxA) : 0.f;
    float eB = (lane < NM) ? __expf(prB - mxB) : 0.f;
#pragma unroll
    for (int o = 4; o; o >>= 1) {
        eA += __shfl_xor_sync(FULL, eA, o);
        eB += __shfl_xor_sync(FULL, eB, o);
    }
    float pbA = __shfl_sync(FULL, prA, bestA);
    float pbB = __shfl_sync(FULL, prB, bestB);

    if (lane == 0) {
        float ceA = (mxA + __logf(eA)) - pbA;
        float ceB = (mxB + __logf(eB)) - pbB;
        float lpA  = fmaxf(__logf(crpA), -100.0f);
        float l1pA = fmaxf(log1pf(-crpA), -100.0f);
        float lpB  = fmaxf(__logf(crpB), -100.0f);
        float l1pB = fmaxf(log1pf(-crpB), -100.0f);
        float bceA = -(cryA * lpA + (1.0f - cryA) * l1pA);
        float bceB = -(cryB * lpB + (1.0f - cryB) * l1pB);
        warp_sums[w] = (ceA + rsA * 0.01f + bceA) + (ceB + rsB * 0.01f + bceB);
    }
    __syncthreads();
    if (threadIdx.x == 0) {
        float t = 0.f;
#pragma unroll
        for (int i = 0; i < WPB; i++) t += warp_sums[i];
        g_partials[blockIdx.x] = t;
        __threadfence();
        unsigned done = atomicAdd(&g_count, 1u);
        is_last = (done == NBLOCKS - 1);
    }
    __syncthreads();

    if (is_last) {
        // deterministic finalize: 256 threads, 4 float4 each in fixed order, fixed tree
        __shared__ float sm[32];
        const float4* p4 = (const float4*)g_partials;   // 1024 float4, L2-hot
        float t = 0.f;
#pragma unroll
        for (int i = 0; i < 4; i++) {
            float4 a = p4[threadIdx.x + i * 256];
            t += ((a.x + a.y) + (a.z + a.w));
        }
#pragma unroll
        for (int o = 16; o; o >>= 1) t += __shfl_xor_sync(FULL, t, o);
        if (lane == 0) sm[w] = t;
        __syncthreads();
        if (w == 0) {
            float v = (lane < WPB) ? sm[lane] : 0.f;
#pragma unroll
            for (int o = 4; o; o >>= 1) v += __shfl_xor_sync(FULL, v, o);
            if (lane == 0) {
                out[0] = v * (1.0f / (float)B_SZ);
                g_count = 0;                           // reset for next graph replay
            }
        }
    }
}

extern "C" void kernel_launch(void* const* d_in, const int* in_sizes, int n_in,
                              void* d_out, int out_size) {
    const float* path_pred = (const float*)d_in[0];
    const float* path_gt   = (const float*)d_in[1];
    const float* cr_pred   = (const float*)d_in[2];
    const float* cr_gt     = (const float*)d_in[3];
    // d_in[4] = log_vars (unused by the reference's returned value)
    combo_fused<<<NBLOCKS, 32 * WPB>>>(path_pred, path_gt, cr_pred, cr_gt, (float*)d_out);
}

// round 10
// speedup vs baseline: 2.6372x; 1.2912x over previous
#include <cuda_runtime.h>
#include <stdint.h>

#define B_SZ 65536
#define NM 5
#define WPB 8
#define SPB (WPB * 2)            // 16 samples per block (2 per warp)
#define NBLOCKS (B_SZ / SPB)     // 4096

__device__ float g_partials[NBLOCKS];
__device__ unsigned g_count;     // zero-init; self-resets every launch

__device__ __forceinline__ float sqrt_ap(float x) {
    float r;
    asm("sqrt.approx.f32 %0, %1;" : "=f"(r) : "f"(x));
    return r;
}

// Smooth-L1 (huber, delta=1): ad<1 ? 0.5 d^2 : ad-0.5 == t*(ad - 0.5t), t=min(ad,1)
__device__ __forceinline__ float huber(float d) {
    float ad = fabsf(d);
    float t = fminf(ad, 1.0f);
    return t * fmaf(-0.5f, t, ad);
}

__device__ __forceinline__ uint32_t rotl32(uint32_t x, uint32_t d) {
    return __funnelshift_l(x, x, d);
}

// JAX partitionable ThreeFry-2x32: key=(0,42), counter=(0,i); randint(0,5) -> (x0^x1) % 5
__device__ __forceinline__ int threefry_mod5(uint32_t i) {
    const uint32_t k0 = 0u, k1 = 42u;
    const uint32_t k2 = k0 ^ k1 ^ 0x1BD11BDAu;
    uint32_t x0 = k0;
    uint32_t x1 = i + k1;
#define TF4(r0, r1, r2, r3)                           \
    x0 += x1; x1 = rotl32(x1, r0); x1 ^= x0;          \
    x0 += x1; x1 = rotl32(x1, r1); x1 ^= x0;          \
    x0 += x1; x1 = rotl32(x1, r2); x1 ^= x0;          \
    x0 += x1; x1 = rotl32(x1, r3); x1 ^= x0;
    TF4(13, 15, 26, 6)   x0 += k1; x1 += k2 + 1u;
    TF4(17, 29, 16, 24)  x0 += k2; x1 += k0 + 2u;
    TF4(13, 15, 26, 6)   x0 += k0; x1 += k1 + 3u;
    TF4(17, 29, 16, 24)  x0 += k1; x1 += k2 + 4u;
    TF4(13, 15, 26, 6)   x0 += k2; x1 += k0 + 5u;
#undef TF4
    return (int)((x0 ^ x1) % 5u);
}

// dist-based argmin over eligible modes (heavy path, ~13% of samples)
// b = tp + 2*lane; off = 0 (sample A) or 505 (sample B)
__device__ __forceinline__ void heavy_best(
    const float* __restrict__ b, int off, float2 g0, float2 g1, bool has2,
    unsigned emask, int& best, float& rs) {
    const unsigned FULL = 0xffffffffu;
    const float INF = __int_as_float(0x7f800000);
    float bestKey = INF;
    best = 0;
#pragma unroll
    for (int m = 0; m < NM; m++) {
        if (emask >> m & 1u) {                 // warp-uniform
            int i = off + m * 100;
            float dx = b[i] - g0.x, dy = b[i + 1] - g0.y;
            float dsum = sqrt_ap(fmaf(dx, dx, dy * dy));
            if (has2) {
                float ex = b[i + 64] - g1.x, ey = b[i + 65] - g1.y;
                dsum += sqrt_ap(fmaf(ex, ex, ey * ey));
            }
#pragma unroll
            for (int o = 16; o; o >>= 1) dsum += __shfl_xor_sync(FULL, dsum, o);
            if (dsum < bestKey) { bestKey = dsum; best = m; }  // strict < = first-min
        }
    }
    int c = off + best * 100;                  // reload true winner (L1/L2-hot)
    rs = huber(b[c] - g0.x) + huber(b[c + 1] - g0.y);
    if (has2) rs += huber(b[c + 64] - g1.x) + huber(b[c + 65] - g1.y);
}

__global__ void __launch_bounds__(32 * WPB, 7)
combo_fused(const float* __restrict__ path_pred,
            const float* __restrict__ path_gt,
            const float* __restrict__ cr_pred,
            const float* __restrict__ cr_gt,
            float* __restrict__ out) {
    __shared__ float warp_sums[WPB];
    __shared__ bool  is_last;
    const unsigned FULL = 0xffffffffu;
    const float INF = __int_as_float(0x7f800000);
    const float COS5 = 0.99619469809174553f;
    int lane = threadIdx.x & 31;
    int w = threadIdx.x >> 5;
    int sA = blockIdx.x * SPB + 2 * w;

    const float* tp = path_pred + (size_t)sA * 505;                  // sample A base; B at +505
    const float2* gt = (const float2*)(path_gt + (size_t)sA * 100);  // A rows; B at +50

    // ---- ThreeFry in-warp (pure ALU, no barrier): lane parity selects sample ----
    int tfv = threefry_mod5((uint32_t)(sA + (lane & 1)));
    int rndA = __shfl_sync(FULL, tfv, 0);
    int rndB = __shfl_sync(FULL, tfv, 1);

    // ---- batch 1: all unconditional loads, lane-split for A/B duplicates ----
    bool has2 = (lane < 18);
    float2 g0A = gt[lane],        g0B = gt[50 + lane];
    float2 g1A = make_float2(0.f, 0.f), g1B = make_float2(0.f, 0.f);
    if (has2) { g1A = gt[32 + lane]; g1B = gt[82 + lane]; }
    float2 refA = gt[49], refB = gt[99];        // uniform -> broadcast loads

    // eligibility lanes: 0..4 = modes of A, 8..12 = modes of B
    bool isB = (lane >= 8);
    int  mlane = lane & 7;                      // mode index within group
    bool eligLane = (mlane < NM) && (lane < 16);
    float ex = 0.f, ey = 0.f, pr = -INF;
    if (eligLane) {
        int base = (isB ? 505 : 0) + mlane * 100 + 98;
        ex = tp[base]; ey = tp[base + 1];
        pr = tp[(isB ? 1005 : 500) + mlane];    // logits
    }
    float crp = 0.f, cry = 0.f;
    if (lane == 0 || lane == 8) {               // BCE inputs: lane0 = A, lane8 = B
        int si = sA + (lane >> 3);
        crp = cr_pred[si]; cry = cr_gt[si];
    }

    // ---- batch 2: speculative huber loads for the rand modes (both samples) ----
    const float* b = tp + 2 * lane;             // shared base; B via +505 offsets
    int iA = rndA * 100;
    int iB = 505 + rndB * 100;
    float sx0A = b[iA], sy0A = b[iA + 1], sx0B = b[iB], sy0B = b[iB + 1];
    float sx1A = 0.f, sy1A = 0.f, sx1B = 0.f, sy1B = 0.f;
    if (has2) {
        sx1A = b[iA + 64]; sy1A = b[iA + 65];
        sx1B = b[iB + 64]; sy1B = b[iB + 65];
    }

    // ---- eligibility, computed once on split lanes ----
    float2 rf = isB ? refB : refA;
    float rn = sqrt_ap(fmaf(rf.x, rf.x, rf.y * rf.y));
    bool elig = false;
    if (eligLane) {
        float tn = sqrt_ap(fmaf(ex, ex, ey * ey));
        float np = rn * tn;
        float dot = fmaf(rf.x, ex, rf.y * ey);
        bool nanm = isnan(rf.x) || isnan(rf.y) || isnan(ex) || isnan(ey);
        elig = nanm ? false : (np == 0.f ? true : (dot >= COS5 * np));
    }
    unsigned em = __ballot_sync(FULL, elig);
    unsigned emA = em & 0x1fu;
    unsigned emB = (em >> 8) & 0x1fu;

    // ---- per-sample best + rsum partial (fast path uses speculative registers) ----
    int bestA, bestB;
    float rsA, rsB;
    if (emA) {
        heavy_best(b, 0, g0A, g1A, has2, emA, bestA, rsA);
    } else {
        bestA = rndA;
        rsA = huber(sx0A - g0A.x) + huber(sy0A - g0A.y);
        if (has2) rsA += huber(sx1A - g1A.x) + huber(sy1A - g1A.y);
    }
    if (emB) {
        heavy_best(b, 505, g0B, g1B, has2, emB, bestB, rsB);
    } else {
        bestB = rndB;
        rsB = huber(sx0B - g0B.x) + huber(sy0B - g0B.y);
        if (has2) rsB += huber(sx1B - g1B.x) + huber(sy1B - g1B.y);
    }

    // interleaved butterflies: A and B latencies overlap
#pragma unroll
    for (int o = 16; o; o >>= 1) {
        rsA += __shfl_xor_sync(FULL, rsA, o);
        rsB += __shfl_xor_sync(FULL, rsB, o);
    }

    // single octet-butterfly log_softmax: octet 0 reduces A logits, octet 1 reduces B
    float mx = pr;
#pragma unroll
    for (int o = 4; o; o >>= 1) mx = fmaxf(mx, __shfl_xor_sync(FULL, mx, o));
    float e = eligLane ? __expf(pr - mx) : 0.f;
#pragma unroll
    for (int o = 4; o; o >>= 1) e += __shfl_xor_sync(FULL, e, o);
    float pbA = __shfl_sync(FULL, pr, bestA);        // lanes 0..4 hold A logits
    float pbB = __shfl_sync(FULL, pr, 8 + bestB);    // lanes 8..12 hold B logits

    // final per-sample scalar on lanes 0 (A) and 8 (B) simultaneously
    float pb = isB ? pbB : pbA;
    float rs = isB ? rsB : rsA;
    float ce = (mx + __logf(e)) - pb;
    float lp  = fmaxf(__logf(crp), -100.0f);
    float l1p = fmaxf(log1pf(-crp), -100.0f);
    float bce = -(cry * lp + (1.0f - cry) * l1p);
    float contrib = ce + rs * 0.01f + bce;           // valid on lanes 0 and 8 only
    float contribB = __shfl_sync(FULL, contrib, 8);

    if (lane == 0) warp_sums[w] = contrib + contribB;
    __syncthreads();
    if (threadIdx.x == 0) {
        float t = 0.f;
#pragma unroll
        for (int i = 0; i < WPB; i++) t += warp_sums[i];
        g_partials[blockIdx.x] = t;
        __threadfence();
        unsigned done = atomicAdd(&g_count, 1u);
        is_last = (done == NBLOCKS - 1);
    }
    __syncthreads();

    if (is_last) {
        // deterministic finalize: 256 threads, 4 float4 each in fixed order, fixed tree
        __shared__ float sm[32];
        const float4* p4 = (const float4*)g_partials;   // 1024 float4, L2-hot
        float t = 0.f;
#pragma unroll
        for (int i = 0; i < 4; i++) {
            float4 a = p4[threadIdx.x + i * 256];
            t += ((a.x + a.y) + (a.z + a.w));
        }
#pragma unroll
        for (int o = 16; o; o >>= 1) t += __shfl_xor_sync(FULL, t, o);
        if (lane == 0) sm[w] = t;
        __syncthreads();
        if (w == 0) {
            float v = (lane < WPB) ? sm[lane] : 0.f;
#pragma unroll
            for (int o = 4; o; o >>= 1) v += __shfl_xor_sync(FULL, v, o);
            if (lane == 0) {
                out[0] = v * (1.0f / (float)B_SZ);
                g_count = 0;                           // reset for next graph replay
            }
        }
    }
}

extern "C" void kernel_launch(void* const* d_in, const int* in_sizes, int n_in,
                              void* d_out, int out_size) {
    const float* path_pred = (const float*)d_in[0];
    const float* path_gt   = (const float*)d_in[1];
    const float* cr_pred   = (const float*)d_in[2];
    const float* cr_gt     = (const float*)d_in[3];
    // d_in[4] = log_vars (unused by the reference's returned value)
    combo_fused<<<NBLOCKS, 32 * WPB>>>(path_pred, path_gt, cr_pred, cr_gt, (float*)d_out);
}